// round 10
// baseline (speedup 1.0000x reference)
#include <cuda_runtime.h>
#include <cuda_bf16.h>
#include <math.h>

#define MAXN 50000
#define MAXE 800000

// ---------------- device scratch ----------------
__device__ __align__(16) float g_qt [(size_t)MAXN * 128];       // x@(WqWk^T) + gvec
__device__ __align__(16) __nv_bfloat16 g_xb[(size_t)MAXN * 64]; // x in bf16 (gather side)
__device__ __align__(16) __nv_bfloat16 g_v [(size_t)MAXN * 128];// projected v, bf16
__device__ __align__(16) float g_agg[(size_t)MAXN * 128];       // attention output
__device__ __align__(16) float g_M  [64 * 128];                 // Mcat = Wq Wk^T per head
__device__ __align__(16) float g_W2 [64 * 64];                  // Wskip @ Wc
__device__ float  g_gvec[128];                                   // Wk_h @ bq_h per head
__device__ float  g_b2[64];                                      // bskip@Wc + bc
__device__ int    g_esrc [MAXE];
__device__ int    g_edst [MAXE];
__device__ int    g_srcs [MAXE];
__device__ int    g_cnt  [MAXN];
__device__ int    g_cur  [MAXN];
__device__ int    g_rowptr[MAXN + 1];
__device__ int    g_blksum[64];
__device__ double g_stats[2];

// ---------------- init ----------------
__global__ void k_init(int n) {
    int i = blockIdx.x * blockDim.x + threadIdx.x;
    if (i < n) { g_cnt[i] = 0; g_cur[i] = 0; }
    if (i == 0) { g_stats[0] = 0.0; g_stats[1] = 0.0; }
}

// ---------------- convert (self-detecting dtype) + fused dst histogram ----------------
// int64 edge data (values < 2^31) has every odd 32-bit word == 0; sniff per block.
__global__ void k_convert(const void* __restrict__ ei, int e) {
    __shared__ int s_is64;
    if (threadIdx.x == 0) {
        const int* w = (const int*)ei;
        int all0 = 1;
        for (int i = 1; i < 64; i += 2) all0 &= (w[i] == 0);
        s_is64 = all0;
    }
    __syncthreads();
    int i = blockIdx.x * blockDim.x + threadIdx.x;
    if (i >= 2 * e) return;
    int v;
    if (s_is64) v = (int)((const long long*)ei)[i];
    else        v = ((const int*)ei)[i];
    if (i < e) g_esrc[i] = v;
    else { g_edst[i - e] = v; atomicAdd(&g_cnt[v], 1); }
}

// ---------------- precomputes, 8 threads/output + shuffle reduce ----------------
__global__ void k_prep(const float* __restrict__ Wq, const float* __restrict__ bq,
                       const float* __restrict__ Wk,
                       const float* __restrict__ Wsk, const float* __restrict__ bsk,
                       const float* __restrict__ Wc, const float* __restrict__ bc) {
    int idx = blockIdx.x * 256 + threadIdx.x;
    int g = idx >> 3, part = idx & 7;
    float s = 0.f;
    int valid = 0;
    float* dst = 0;
    if (g < 8192) {                      // Mcat[i][h*64+j] = sum_c Wq[i][h64+c]*Wk[j][h64+c]
        int i = g >> 7, col = g & 127, h = col >> 6, j = col & 63;
        const float* wq = Wq + i * 128 + h * 64 + part * 8;
        const float* wk = Wk + j * 128 + h * 64 + part * 8;
#pragma unroll
        for (int c = 0; c < 8; c++) s = fmaf(wq[c], wk[c], s);
        dst = &g_M[g]; valid = 1;
    } else if (g < 12288) {              // W2 = Wskip @ Wc
        int o = g - 8192, r = o >> 6, c = o & 63;
#pragma unroll
        for (int k = 0; k < 16; k++)
            s = fmaf(Wsk[r * 128 + part * 16 + k], Wc[(part * 16 + k) * 64 + c], s);
        dst = &g_W2[o]; valid = 1;
    } else if (g < 12352) {              // b2 = bskip@Wc + bc
        int c = g - 12288;
        if (part == 0) s = bc[c];
#pragma unroll
        for (int k = 0; k < 16; k++)
            s = fmaf(bsk[part * 16 + k], Wc[(part * 16 + k) * 64 + c], s);
        dst = &g_b2[c]; valid = 1;
    } else if (g < 12480) {              // gvec[h*64+i] = sum_j Wk[i][h64+j]*bq[h64+j]
        int o = g - 12352, h = o >> 6, i = o & 63;
#pragma unroll
        for (int j = 0; j < 8; j++)
            s = fmaf(Wk[i * 128 + h * 64 + part * 8 + j], bq[h * 64 + part * 8 + j], s);
        dst = &g_gvec[o]; valid = 1;
    }
    s += __shfl_xor_sync(0xffffffffu, s, 1);
    s += __shfl_xor_sync(0xffffffffu, s, 2);
    s += __shfl_xor_sync(0xffffffffu, s, 4);
    if (valid && part == 0) *dst = s;
}

// ---------------- x -> bf16 copy ----------------
__global__ void k_xb(const float* __restrict__ x, int n) {
    int i = blockIdx.x * 256 + threadIdx.x;
    if (i < n * 16) {
        float4 xv = ((const float4*)x)[i];
        __nv_bfloat162 lo = __floats2bfloat162_rn(xv.x, xv.y);
        __nv_bfloat162 hi = __floats2bfloat162_rn(xv.z, xv.w);
        uint2 u;
        u.x = *(unsigned*)&lo;
        u.y = *(unsigned*)&hi;
        ((uint2*)g_xb)[i] = u;
    }
}

// ---------------- projections: qt = x@Mcat + gvec (fp32), v = x@Wv+bv (bf16) ----------------
__global__ void __launch_bounds__(256) k_gemm2(
        const float* __restrict__ x,
        const float* __restrict__ Wv, const float* __restrict__ bv,
        int n) {
    __shared__ float Xs[32][68];
    __shared__ float Ws[32][128];
    int m = blockIdx.y;
    const float* W    = (m == 0) ? (const float*)g_M : Wv;
    const float* bias = (m == 0) ? (const float*)g_gvec : bv;

    int tx = threadIdx.x & 31;
    int ty = threadIdx.x >> 5;
    int row0 = blockIdx.x * 64;

    float acc[8][4];
#pragma unroll
    for (int i = 0; i < 8; i++)
#pragma unroll
        for (int j = 0; j < 4; j++) acc[i][j] = 0.f;

    for (int kc = 0; kc < 2; kc++) {
#pragma unroll
        for (int it = 0; it < 2; it++) {
            int idx = threadIdx.x + it * 256;
            int r = idx >> 3, kq = idx & 7;
            float4 xv = make_float4(0.f, 0.f, 0.f, 0.f);
            if (row0 + r < n) xv = ((const float4*)x)[(size_t)(row0 + r) * 16 + kc * 8 + kq];
            Xs[kq * 4 + 0][r] = xv.x;
            Xs[kq * 4 + 1][r] = xv.y;
            Xs[kq * 4 + 2][r] = xv.z;
            Xs[kq * 4 + 3][r] = xv.w;
        }
#pragma unroll
        for (int it = 0; it < 4; it++) {
            int idx = threadIdx.x + it * 256;
            ((float4*)Ws)[idx] = ((const float4*)W)[kc * 1024 + idx];
        }
        __syncthreads();
#pragma unroll
        for (int k = 0; k < 32; k++) {
            float4 a0 = *(const float4*)&Xs[k][ty * 8];
            float4 a1 = *(const float4*)&Xs[k][ty * 8 + 4];
            float4 b  = *(const float4*)&Ws[k][tx * 4];
            float af[8] = {a0.x, a0.y, a0.z, a0.w, a1.x, a1.y, a1.z, a1.w};
#pragma unroll
            for (int i = 0; i < 8; i++) {
                acc[i][0] = fmaf(af[i], b.x, acc[i][0]);
                acc[i][1] = fmaf(af[i], b.y, acc[i][1]);
                acc[i][2] = fmaf(af[i], b.z, acc[i][2]);
                acc[i][3] = fmaf(af[i], b.w, acc[i][3]);
            }
        }
        __syncthreads();
    }
    float4 bv4 = *(const float4*)&bias[tx * 4];
    if (m == 0) {
#pragma unroll
        for (int i = 0; i < 8; i++) {
            int r = row0 + ty * 8 + i;
            if (r < n)
                *(float4*)&g_qt[(size_t)r * 128 + tx * 4] =
                    make_float4(acc[i][0] + bv4.x, acc[i][1] + bv4.y,
                                acc[i][2] + bv4.z, acc[i][3] + bv4.w);
        }
    } else {
#pragma unroll
        for (int i = 0; i < 8; i++) {
            int r = row0 + ty * 8 + i;
            if (r < n) {
                __nv_bfloat162 lo = __floats2bfloat162_rn(acc[i][0] + bv4.x, acc[i][1] + bv4.y);
                __nv_bfloat162 hi = __floats2bfloat162_rn(acc[i][2] + bv4.z, acc[i][3] + bv4.w);
                uint2 u;
                u.x = *(unsigned*)&lo;
                u.y = *(unsigned*)&hi;
                *(uint2*)&g_v[(size_t)r * 128 + tx * 4] = u;
            }
        }
    }
}

// ---------------- CSR scan ----------------
__global__ void k_scan1(int n) {
    __shared__ int sh[1024];
    int tid = threadIdx.x;
    int i = blockIdx.x * 1024 + tid;
    int v = (i < n) ? g_cnt[i] : 0;
    sh[tid] = v;
    __syncthreads();
    for (int off = 1; off < 1024; off <<= 1) {
        int t = (tid >= off) ? sh[tid - off] : 0;
        __syncthreads();
        sh[tid] += t;
        __syncthreads();
    }
    if (i < n) g_rowptr[i] = sh[tid] - v;
    if (tid == 1023) g_blksum[blockIdx.x] = sh[1023];
}

__global__ void k_scan2(int nb, int n) {
    if (threadIdx.x == 0 && blockIdx.x == 0) {
        int acc = 0;
        for (int b = 0; b < nb; b++) { int t = g_blksum[b]; g_blksum[b] = acc; acc += t; }
        g_rowptr[n] = acc;
    }
}

__global__ void k_scan3(int n) {
    int i = blockIdx.x * 1024 + threadIdx.x;
    if (i < n) g_rowptr[i] += g_blksum[blockIdx.x];
}

__global__ void k_scatter(int e) {
    int i = blockIdx.x * blockDim.x + threadIdx.x;
    if (i < e) {
        int dst = g_edst[i];
        int pos = g_rowptr[dst] + atomicAdd(&g_cur[dst], 1);
        g_srcs[pos] = g_esrc[i];
    }
}

// ---------------- attention: software-pipelined gather, one warp per dst ----------------
// Pipeline: indices prefetched 2 iters ahead; X/V gathers issued 1 iter ahead.
// Masked (predicated) slots make the loop uniform; fallback address = g_srcs[beg] (valid).
__device__ __forceinline__ float2 bf2f(unsigned u) {
    return __bfloat1622float2(*(__nv_bfloat162*)&u);
}

__global__ void __launch_bounds__(128) k_attn(int n) {
    int node = blockIdx.x * 4 + (threadIdx.x >> 5);
    if (node >= n) return;
    int lane = threadIdx.x & 31;
    int l15 = lane & 15;

    float4 qt = *(const float4*)&g_qt[(size_t)node * 128 + lane * 4];
    int beg = g_rowptr[node], end = g_rowptr[node + 1];
    int deg = end - beg;

    const uint2* xb = (const uint2*)g_xb;
    const uint2* vb = (const uint2*)g_v;

    float denom = 0.f;
    float4 acc = make_float4(0.f, 0.f, 0.f, 0.f);

    if (deg > 0) {
        int nIter = (deg + 3) >> 2;

        int sB[4];
        float mA[4], mB[4];
        uint2 XA[4], VA[4];

        // stage 0: indices + gathers for iter 0
#pragma unroll
        for (int j = 0; j < 4; j++) {
            int p = (j < deg);
            int a = g_srcs[p ? beg + j : beg];
            mA[j] = p ? 1.f : 0.f;
            XA[j] = xb[(size_t)a * 16 + l15];
            VA[j] = vb[(size_t)a * 32 + lane];
        }
        // stage 1: indices for iter 1
#pragma unroll
        for (int j = 0; j < 4; j++) {
            int o = 4 + j;
            int p = (o < deg);
            sB[j] = g_srcs[p ? beg + o : beg];
            mB[j] = p ? 1.f : 0.f;
        }

        for (int it = 0; it < nIter; it++) {
            // issue gathers for it+1 (dead on the last iteration; masked anyway)
            uint2 XN[4], VN[4];
#pragma unroll
            for (int j = 0; j < 4; j++) {
                XN[j] = xb[(size_t)sB[j] * 16 + l15];
                VN[j] = vb[(size_t)sB[j] * 32 + lane];
            }
            // prefetch indices for it+2
            int sC[4];
            float mC[4];
#pragma unroll
            for (int j = 0; j < 4; j++) {
                int o = (it + 2) * 4 + j;
                int p = (o < deg);
                sC[j] = g_srcs[p ? beg + o : beg];
                mC[j] = p ? 1.f : 0.f;
            }
            // compute on A (in-flight since last iteration)
            float d[4];
#pragma unroll
            for (int j = 0; j < 4; j++) {
                float2 a = bf2f(XA[j].x), b = bf2f(XA[j].y);
                d[j] = qt.x * a.x + qt.y * a.y + qt.z * b.x + qt.w * b.y;
            }
#pragma unroll
            for (int off = 8; off > 0; off >>= 1) {
                d[0] += __shfl_xor_sync(0xffffffffu, d[0], off);
                d[1] += __shfl_xor_sync(0xffffffffu, d[1], off);
                d[2] += __shfl_xor_sync(0xffffffffu, d[2], off);
                d[3] += __shfl_xor_sync(0xffffffffu, d[3], off);
            }
            float w[4];
#pragma unroll
            for (int j = 0; j < 4; j++) w[j] = __expf(d[j] * 0.125f) * mA[j];
            denom += (w[0] + w[1]) + (w[2] + w[3]);
#pragma unroll
            for (int j = 0; j < 4; j++) {
                float2 a = bf2f(VA[j].x), b = bf2f(VA[j].y);
                acc.x = fmaf(w[j], a.x, acc.x);
                acc.y = fmaf(w[j], a.y, acc.y);
                acc.z = fmaf(w[j], b.x, acc.z);
                acc.w = fmaf(w[j], b.y, acc.w);
            }
            // rotate pipeline registers
#pragma unroll
            for (int j = 0; j < 4; j++) {
                XA[j] = XN[j]; VA[j] = VN[j];
                mA[j] = mB[j];
                sB[j] = sC[j]; mB[j] = mC[j];
            }
        }
    }
    float inv = 1.f / (denom + 1e-16f);
    acc.x *= inv; acc.y *= inv; acc.z *= inv; acc.w *= inv;
    ((float4*)g_agg)[(size_t)node * 32 + lane] = acc;
}

// ---------------- final: out = agg@Wc + x@W2 + b2, fused LN stats ----------------
__global__ void __launch_bounds__(256) k_final(const float* __restrict__ x,
                                               const float* __restrict__ Wc,
                                               float* __restrict__ out, int n) {
    __shared__ float Xs[32][132];
    __shared__ float Ws[32][64];
    __shared__ float rs[8], rss[8];

    int tx = threadIdx.x & 15;
    int ty = threadIdx.x >> 4;
    int row0 = blockIdx.x * 128;

    float acc[8][4];
#pragma unroll
    for (int i = 0; i < 8; i++)
#pragma unroll
        for (int j = 0; j < 4; j++) acc[i][j] = 0.f;

    for (int kc = 0; kc < 6; kc++) {
#pragma unroll
        for (int it = 0; it < 4; it++) {
            int idx = threadIdx.x + it * 256;
            int r = idx >> 3, kq = idx & 7;
            float4 av = make_float4(0.f, 0.f, 0.f, 0.f);
            if (row0 + r < n) {
                if (kc < 4) av = ((const float4*)g_agg)[(size_t)(row0 + r) * 32 + kc * 8 + kq];
                else        av = ((const float4*)x)[(size_t)(row0 + r) * 16 + (kc - 4) * 8 + kq];
            }
            Xs[kq * 4 + 0][r] = av.x;
            Xs[kq * 4 + 1][r] = av.y;
            Xs[kq * 4 + 2][r] = av.z;
            Xs[kq * 4 + 3][r] = av.w;
        }
#pragma unroll
        for (int it = 0; it < 2; it++) {
            int idx = threadIdx.x + it * 256;
            int k = idx >> 4, c4 = idx & 15;
            float4 wv;
            if (kc < 4) wv = ((const float4*)Wc)[(kc * 32 + k) * 16 + c4];
            else        wv = ((const float4*)g_W2)[((kc - 4) * 32 + k) * 16 + c4];
            *(float4*)&Ws[k][c4 * 4] = wv;
        }
        __syncthreads();
#pragma unroll
        for (int k = 0; k < 32; k++) {
            float4 a0 = *(const float4*)&Xs[k][ty * 8];
            float4 a1 = *(const float4*)&Xs[k][ty * 8 + 4];
            float4 b  = *(const float4*)&Ws[k][tx * 4];
            float af[8] = {a0.x, a0.y, a0.z, a0.w, a1.x, a1.y, a1.z, a1.w};
#pragma unroll
            for (int i = 0; i < 8; i++) {
                acc[i][0] = fmaf(af[i], b.x, acc[i][0]);
                acc[i][1] = fmaf(af[i], b.y, acc[i][1]);
                acc[i][2] = fmaf(af[i], b.z, acc[i][2]);
                acc[i][3] = fmaf(af[i], b.w, acc[i][3]);
            }
        }
        __syncthreads();
    }

    float4 b2 = *(const float4*)&g_b2[tx * 4];
    float s = 0.f, ss = 0.f;
#pragma unroll
    for (int i = 0; i < 8; i++) {
        int r = row0 + ty * 8 + i;
        if (r < n) {
            float4 o = make_float4(acc[i][0] + b2.x, acc[i][1] + b2.y,
                                   acc[i][2] + b2.z, acc[i][3] + b2.w);
            *(float4*)&out[(size_t)r * 64 + tx * 4] = o;
            s += (o.x + o.y) + (o.z + o.w);
            ss += o.x * o.x + o.y * o.y + o.z * o.z + o.w * o.w;
        }
    }
#pragma unroll
    for (int off = 16; off > 0; off >>= 1) {
        s  += __shfl_xor_sync(0xffffffffu, s, off);
        ss += __shfl_xor_sync(0xffffffffu, ss, off);
    }
    int wid = threadIdx.x >> 5, lane = threadIdx.x & 31;
    if (lane == 0) { rs[wid] = s; rss[wid] = ss; }
    __syncthreads();
    if (threadIdx.x == 0) {
        double S = 0.0, SS = 0.0;
        for (int w = 0; w < 8; w++) { S += (double)rs[w]; SS += (double)rss[w]; }
        atomicAdd(&g_stats[0], S);
        atomicAdd(&g_stats[1], SS);
    }
}

// ---------------- graph-level LayerNorm ----------------
__global__ void k_norm(float* __restrict__ out, const float* __restrict__ gamma,
                       const float* __restrict__ beta, int total) {
    int i = blockIdx.x * blockDim.x + threadIdx.x;
    if (i < total) {
        double M = (double)total;
        double mean = g_stats[0] / M;
        double var  = g_stats[1] / M - mean * mean;
        if (var < 0.0) var = 0.0;
        float stdv = (float)sqrt(var);
        float v = out[i];
        int d = i & 63;
        out[i] = (v - (float)mean) / (stdv + 1e-5f) * __ldg(&gamma[d]) + __ldg(&beta[d]);
    }
}

// ---------------- launch ----------------
extern "C" void kernel_launch(void* const* d_in, const int* in_sizes, int n_in,
                              void* d_out, int out_size) {
    const float* x    = (const float*)d_in[0];
    const void*  ei   = d_in[1];
    const float* Wq   = (const float*)d_in[2];
    const float* bq   = (const float*)d_in[3];
    const float* Wk   = (const float*)d_in[4];
    const float* Wv   = (const float*)d_in[6];
    const float* bv   = (const float*)d_in[7];
    const float* Wsk  = (const float*)d_in[8];
    const float* bsk  = (const float*)d_in[9];
    const float* Wc   = (const float*)d_in[10];
    const float* bc   = (const float*)d_in[11];
    const float* gam  = (const float*)d_in[12];
    const float* bet  = (const float*)d_in[13];
    float* out = (float*)d_out;

    int n = in_sizes[0] / 64;
    int e = in_sizes[1] / 2;

    k_init<<<(n + 255) / 256, 256>>>(n);
    k_convert<<<(2 * e + 255) / 256, 256>>>(ei, e);
    k_prep<<<390, 256>>>(Wq, bq, Wk, Wsk, bsk, Wc, bc);
    k_xb<<<(n * 16 + 255) / 256, 256>>>(x, n);
    k_gemm2<<<dim3((n + 63) / 64, 2), 256>>>(x, Wv, bv, n);
    int nb = (n + 1023) / 1024;
    k_scan1<<<nb, 1024>>>(n);
    k_scan2<<<1, 32>>>(nb, n);
    k_scan3<<<nb, 1024>>>(n);
    k_scatter<<<(e + 255) / 256, 256>>>(e);
    k_attn<<<(n + 3) / 4, 128>>>(n);
    k_final<<<(n + 127) / 128, 256>>>(x, Wc, out, n);
    k_norm<<<(n * 64 + 255) / 256, 256>>>(out, gam, bet, n * 64);
}